// round 9
// baseline (speedup 1.0000x reference)
#include <cuda_runtime.h>
#include <cstdint>

// GTConvAE — fused persistent kernel, R9.
// Kronecker identity: S^k x[tau] = sum_{a,b<3} c_k[a][b] * Sg^b x[(tau-a) mod t].
// Layer = two GEMMs (G1=Sg@act, G2=Sg2@act) + 9-term combine with folded filters.
// Encoder fuses maxpool+relu; decoder exploits zero-stuffed upsampling.
// R9: 128 blocks x 256 threads (8 warps/SM, 2/SMSP), 24m x 32j single-pass GEMM
// tiles (A reads broadcast, B conflict-free), scalar 192-thread combines.

#define NN  192
#define TT  32
#define NB  128
#define KS  196   // smem row stride in floats (float4 aligned; conflict-free phases)

// ---------------- scratch --------------------------------------------------------
__device__ float g_Sg2 [NN * NN];
__device__ float g_G1  [256 * NN];   // act-layout [j][n]; also P = Sg@X for e1
__device__ float g_G2  [256 * NN];
__device__ float g_actA[256 * NN];
__device__ float g_actB[256 * NN];
__device__ unsigned g_cnt = 0;
__device__ unsigned g_gen = 0;

// ---------------- grid barrier: release-arrive / acquire-poll --------------------
__device__ __forceinline__ void grid_barrier()
{
    __syncthreads();
    if (threadIdx.x == 0) {
        unsigned gen;
        asm volatile("ld.relaxed.gpu.u32 %0, [%1];"
                     : "=r"(gen) : "l"(&g_gen) : "memory");
        unsigned prev;
        asm volatile("atom.release.gpu.add.u32 %0, [%1], %2;"
                     : "=r"(prev) : "l"(&g_cnt), "r"(1u) : "memory");
        if (prev == NB - 1) {
            asm volatile("st.relaxed.gpu.u32 [%0], %1;"
                         :: "l"(&g_cnt), "r"(0u) : "memory");
            asm volatile("st.release.gpu.u32 [%0], %1;"
                         :: "l"(&g_gen), "r"(gen + 1u) : "memory");
        } else {
            unsigned cur;
            do {
                __nanosleep(16);
                asm volatile("ld.acquire.gpu.u32 %0, [%1];"
                             : "=r"(cur) : "l"(&g_gen) : "memory");
            } while (cur == gen);
        }
    }
    __syncthreads();
}

// ---------------- cp.async helpers ----------------------------------------------
__device__ __forceinline__ void cp16(float* dst, const float* src, bool cg)
{
    uint32_t d = (uint32_t)__cvta_generic_to_shared(dst);
    if (cg)
        asm volatile("cp.async.cg.shared.global [%0], [%1], 16;" :: "r"(d), "l"(src));
    else
        asm volatile("cp.async.ca.shared.global [%0], [%1], 16;" :: "r"(d), "l"(src));
}
__device__ __forceinline__ void cp_wait_all()
{
    asm volatile("cp.async.wait_all;" ::: "memory");
}

// ---------------- tile loaders (256 threads) -------------------------------------
// A band: 24 rows x 192 k -> As[m][k]   (1152 float4 ops)
__device__ __forceinline__ void loadA24(const float* __restrict__ A, int m0,
                                        bool cg, float* As)
{
    #pragma unroll
    for (int r = 0; r < 5; r++) {
        int op = threadIdx.x + 256 * r;
        if (op < 1152) {
            int ml = op / 48, kq = op - ml * 48;
            cp16(&As[ml * KS + 4 * kq], &A[(m0 + ml) * NN + 4 * kq], cg);
        }
    }
}
// B tile (act layout [j*NN+k]): 32 rows x 192 k -> Bs[j][k]  (1536 float4 ops)
__device__ __forceinline__ void loadB32(const float* __restrict__ Bg, int j0,
                                        float* Bs)
{
    #pragma unroll
    for (int r = 0; r < 6; r++) {
        int op = threadIdx.x + 256 * r;
        int jl = op / 48, kq = op - jl * 48;
        cp16(&Bs[jl * KS + 4 * kq], &Bg[(j0 + jl) * NN + 4 * kq], true);
    }
}

// ---------------- compute one 24m x 32j tile (256 threads) -----------------------
// Warp lanes share ty -> A LDS broadcast; B LDS.128 conflict-free per phase.
template <bool CROW>
__device__ __forceinline__ void tile_compute(const float* __restrict__ As,
                                             const float* __restrict__ Bs,
                                             float* __restrict__ C, int m0, int j0)
{
    const int tid = threadIdx.x;
    const int tx = tid & 31, ty = tid >> 5;      // j col, m base (0..7)
    float acc0 = 0.f, acc1 = 0.f, acc2 = 0.f;
    const float* bp  = Bs + tx * KS;
    const float* ap0 = As + ty * KS;
    const float* ap1 = ap0 + 8 * KS;
    const float* ap2 = ap0 + 16 * KS;
    #pragma unroll 8
    for (int k = 0; k < NN; k += 4) {
        float4 b  = *(const float4*)(bp + k);
        float4 a0 = *(const float4*)(ap0 + k);
        float4 a1 = *(const float4*)(ap1 + k);
        float4 a2 = *(const float4*)(ap2 + k);
        acc0 += a0.x * b.x; acc0 += a0.y * b.y; acc0 += a0.z * b.z; acc0 += a0.w * b.w;
        acc1 += a1.x * b.x; acc1 += a1.y * b.y; acc1 += a1.z * b.z; acc1 += a1.w * b.w;
        acc2 += a2.x * b.x; acc2 += a2.y * b.y; acc2 += a2.z * b.z; acc2 += a2.w * b.w;
    }
    const int j = j0 + tx;
    if (CROW) {
        C[(m0 + ty     ) * NN + j] = acc0;
        C[(m0 + ty +  8) * NN + j] = acc1;
        C[(m0 + ty + 16) * NN + j] = acc2;
    } else {
        C[j * NN + m0 + ty     ] = acc0;
        C[j * NN + m0 + ty +  8] = acc1;
        C[j * NN + m0 + ty + 16] = acc2;
    }
}

// ---------------- big GEMM stage: one 24m x 32j tile -----------------------------
template <bool LOADA>
__device__ void big_stage(const float* __restrict__ A, bool acg,
                          const float* __restrict__ Bact,
                          float* __restrict__ C, int m0, int j0,
                          float* As, float* Bs)
{
    if (LOADA) loadA24(A, m0, acg, As);
    loadB32(Bact, j0, Bs);
    cp_wait_all(); __syncthreads();
    tile_compute<false>(As, Bs, C, m0, j0);
}

// ---------------- S0 tile: B from column-slices (Sg or X) ------------------------
template <int BMODE, bool CROW>   // BMODE 1: Sg [k*NN+j], 2: X [k*TT+j]
__device__ void s0_tile(const float* __restrict__ A, const float* __restrict__ Bg,
                        int j0, float* __restrict__ C, int m0,
                        float* As, float* Bs)
{
    loadA24(A, m0, false, As);
    const int tid = threadIdx.x;
    #pragma unroll
    for (int r = 0; r < 24; r++) {
        int idx = tid + 256 * r;                 // 0..6143
        int jl = idx & 31, kk = idx >> 5;
        Bs[jl * KS + kk] = (BMODE == 1) ? Bg[kk * NN + j0 + jl]
                                        : Bg[kk * TT + j0 + jl];
    }
    cp_wait_all(); __syncthreads();
    tile_compute<CROW>(As, Bs, C, m0, j0);
}

// ---------------- folded filters -------------------------------------------------
__device__ __forceinline__ float fold_H(const float* __restrict__ h3,
                                        const float sv[4], int a, int b)
{
    float c0 = (a == 0 && b == 0) ? 1.f : 0.f;
    float c1 = (a < 2 && b < 2) ? sv[a * 2 + b] : 0.f;
    float c2 = 0.f;
    #pragma unroll
    for (int a1 = 0; a1 < 2; a1++)
        #pragma unroll
        for (int b1 = 0; b1 < 2; b1++) {
            int a2 = a - a1, b2 = b - b1;
            if (a2 >= 0 && a2 < 2 && b2 >= 0 && b2 < 2)
                c2 += sv[a1 * 2 + b1] * sv[a2 * 2 + b2];
        }
    return h3[0] * c0 + h3[1] * c1 + h3[2] * c2;
}

__device__ __forceinline__ void build_Hs(float* Hs, const float* __restrict__ h,
                                         const float sv[4], int CI, int OT, int ob)
{
    for (int idx = threadIdx.x; idx < CI * 9 * OT; idx += 256) {
        int oo = idx % OT;
        int tmp = idx / OT;
        int b = tmp % 3, a = (tmp / 3) % 3, i = tmp / 9;
        Hs[idx] = fold_H(&h[((ob + oo) * CI + i) * 3], sv, a, b);
    }
}

// ---------------- encoder combine (e2): scalar, 192 threads ----------------------
template <int CI, int CO, int OT>
__device__ __noinline__ void combine_enc(
    const float* __restrict__ G0, const float* __restrict__ G1,
    const float* __restrict__ G2,
    const float* __restrict__ h, const float* __restrict__ sp,
    float* __restrict__ out, int t, int tp, int ob, float* Hs)
{
    const int tid = threadIdx.x;
    const float sv[4] = { sp[0], sp[1], sp[2], sp[3] };
    build_Hs(Hs, h, sv, CI, OT, ob);
    __syncthreads();
    if (tid < NN) {
        const int n = tid;
        float acc0[OT], acc1[OT];
        #pragma unroll
        for (int o = 0; o < OT; o++) { acc0[o] = 0.f; acc1[o] = 0.f; }
        #pragma unroll
        for (int tt = 0; tt < 4; tt++) {
            int src = (2 * tp - 2 + tt + t) & (t - 1);
            #pragma unroll
            for (int i = 0; i < CI; i++) {
                float v0 = __ldcg(&G0[(src * CI + i) * NN + n]);
                float v1 = __ldcg(&G1[(src * CI + i) * NN + n]);
                float v2 = __ldcg(&G2[(src * CI + i) * NN + n]);
                if (tt <= 2) {
                    const float* Hp = &Hs[(i * 3 + (2 - tt)) * 3 * OT];
                    #pragma unroll
                    for (int o = 0; o < OT; o++)
                        acc0[o] += Hp[o] * v0 + Hp[OT + o] * v1 + Hp[2 * OT + o] * v2;
                }
                if (tt >= 1) {
                    const float* Hp = &Hs[(i * 3 + (3 - tt)) * 3 * OT];
                    #pragma unroll
                    for (int o = 0; o < OT; o++)
                        acc1[o] += Hp[o] * v0 + Hp[OT + o] * v1 + Hp[2 * OT + o] * v2;
                }
            }
        }
        #pragma unroll
        for (int o = 0; o < OT; o++)
            out[(tp * CO + ob + o) * NN + n] = fmaxf(fmaxf(acc0[o], acc1[o]), 0.f);
    }
}

// ---------------- decoder combine: scalar, 192 threads ---------------------------
template <int CI, int CO, int OT>
__device__ __noinline__ void combine_dec(
    const float* __restrict__ G0, const float* __restrict__ G1,
    const float* __restrict__ G2,
    const float* __restrict__ h, const float* __restrict__ sp,
    float* __restrict__ out, int t, int tau, int ob, float* Hs)
{
    const int tid = threadIdx.x;
    const float sv[4] = { sp[0], sp[1], sp[2], sp[3] };
    build_Hs(Hs, h, sv, CI, OT, ob);
    __syncthreads();
    if (tid < NN) {
        const int n = tid;
        float acc[OT];
        #pragma unroll
        for (int o = 0; o < OT; o++) acc[o] = 0.f;
        #pragma unroll
        for (int a = 0; a < 3; a++) {
            int src = tau - a; if (src < 0) src += t;
            if (src & 1) continue;             // zero-stuffed upsample
            int tl = src >> 1;
            #pragma unroll 16
            for (int i = 0; i < CI; i++) {
                float v0 = __ldcg(&G0[(tl * CI + i) * NN + n]);
                float v1 = __ldcg(&G1[(tl * CI + i) * NN + n]);
                float v2 = __ldcg(&G2[(tl * CI + i) * NN + n]);
                const float* Hp = &Hs[(i * 3 + a) * 3 * OT];
                #pragma unroll
                for (int o = 0; o < OT; o++)
                    acc[o] += Hp[o] * v0 + Hp[OT + o] * v1 + Hp[2 * OT + o] * v2;
            }
        }
        #pragma unroll
        for (int o = 0; o < OT; o++)
            out[(tau * CO + ob + o) * NN + n] = fmaxf(acc[o], 0.f);
    }
}

// ---------------- persistent mega-kernel ----------------------------------------
__global__ __launch_bounds__(256, 1) void mega(
    const float* __restrict__ X,    const float* __restrict__ Sg,
    const float* __restrict__ s,    const float* __restrict__ h_e1,
    const float* __restrict__ h_e2, const float* __restrict__ h_d1,
    const float* __restrict__ h_d2, float* __restrict__ out)
{
    __shared__ float As[24 * KS];    // 18.8 KB — A band, persistent across S3/S5/S7
    __shared__ float Bs[32 * KS];    // 25.1 KB
    __shared__ float Hs[576];        //  2.3 KB
    __shared__ float G2s[96];        //  e1 mini-GEMM result (4 src x 24 n)

    const int bid = blockIdx.x;
    const int tid = threadIdx.x;

    // big-GEMM identity (fixed across S3/S5/S7)
    const int mat = bid >> 6;                 // 0: Sg, 1: Sg2
    const int sub = bid & 63;
    const int gm0 = (sub >> 3) * 24;          // 8 m-bands of 24
    const int gj0 = (sub & 7) * 32;           // 8 j-tiles of 32

    // ======== S0: Sg2 (48 tiles) + P = Sg@X (8 tiles) ========
    if (bid < 48) {
        int mb = bid / 6, jt = bid % 6;
        s0_tile<1, true>(Sg, Sg, jt * 32, g_Sg2, mb * 24, As, Bs);
    } else if (bid < 56) {
        int mb = bid - 48;
        s0_tile<2, false>(Sg, X, 0, g_G1, mb * 24, As, Bs);
    }
    grid_barrier();

    // ======== S1': e1 combine with fused mini-GEMM for G2 ========
    // 128 blocks = 16 tp x 8 n-bands of 24.
    {
        const int tp = bid & 15, nb = bid >> 4;
        const int n0 = nb * 24;
        loadA24(Sg, n0, false, As);           // Sg rows n0..n0+23
        if (tid < 192) {                      // P rows for the 4 source taus
            int ttl = tid / 48, kq = tid - ttl * 48;
            int src = (2 * tp - 2 + ttl + TT) & (TT - 1);
            cp16(&Bs[ttl * KS + 4 * kq], &g_G1[src * NN + 4 * kq], true);
        }
        const float sv[4] = { s[0], s[1], s[2], s[3] };
        if (tid < 144) {                      // CI=1, OT=16: Hs[(a*3+b)*16+o]
            int o = tid & 15, ab = tid >> 4;
            Hs[tid] = fold_H(&h_e1[o * 3], sv, ab / 3, ab % 3);
        }
        cp_wait_all(); __syncthreads();
        if (tid < 96) {                       // mini-GEMM: 24 n x 4 src
            int nl = tid % 24, st = tid / 24;
            float acc = 0.f;
            const float* ap = As + nl * KS;
            const float* bp = Bs + st * KS;
            #pragma unroll 12
            for (int k = 0; k < NN; k += 4) {
                float4 a = *(const float4*)(ap + k);
                float4 b = *(const float4*)(bp + k);
                acc += a.x * b.x; acc += a.y * b.y; acc += a.z * b.z; acc += a.w * b.w;
            }
            G2s[st * 24 + nl] = acc;
        }
        __syncthreads();
        if (tid < 96) {                       // combine: 24 n x 4 o-groups of 4
            int nl = tid % 24, og = tid / 24;
            int n = n0 + nl;
            float acc0[4] = {0.f, 0.f, 0.f, 0.f};
            float acc1[4] = {0.f, 0.f, 0.f, 0.f};
            #pragma unroll
            for (int ttl = 0; ttl < 4; ttl++) {
                int src = (2 * tp - 2 + ttl + TT) & (TT - 1);
                float v0 = X[n * TT + src];
                float v1 = Bs[ttl * KS + n];       // P[src][n]
                float v2 = G2s[ttl * 24 + nl];
                if (ttl <= 2) {
                    int a = 2 - ttl;
                    #pragma unroll
                    for (int oo = 0; oo < 4; oo++) {
                        int o = og * 4 + oo;
                        acc0[oo] += Hs[(a * 3 + 0) * 16 + o] * v0
                                  + Hs[(a * 3 + 1) * 16 + o] * v1
                                  + Hs[(a * 3 + 2) * 16 + o] * v2;
                    }
                }
                if (ttl >= 1) {
                    int a = 3 - ttl;
                    #pragma unroll
                    for (int oo = 0; oo < 4; oo++) {
                        int o = og * 4 + oo;
                        acc1[oo] += Hs[(a * 3 + 0) * 16 + o] * v0
                                  + Hs[(a * 3 + 1) * 16 + o] * v1
                                  + Hs[(a * 3 + 2) * 16 + o] * v2;
                    }
                }
            }
            #pragma unroll
            for (int oo = 0; oo < 4; oo++) {
                int o = og * 4 + oo;
                g_actA[(tp * 16 + o) * NN + n] = fmaxf(fmaxf(acc0[oo], acc1[oo]), 0.f);
            }
        }
    }
    grid_barrier();

    // ======== S3: e2 GEMMs (load persistent A band) ========
    if (mat == 0)
        big_stage<true>(Sg, false, g_actA, g_G1, gm0, gj0, As, Bs);
    else
        big_stage<true>(g_Sg2, true, g_actA, g_G2, gm0, gj0, As, Bs);
    grid_barrier();

    // ======== S4: combine e2 -> actB ========
    {
        int tp = bid & 7, obg = bid >> 3;      // 16 groups of OT=2
        combine_enc<16, 32, 2>(g_actA, g_G1, g_G2, h_e2, s,
                               g_actB, 16, tp, obg * 2, Hs);
    }
    grid_barrier();

    // ======== S5: d1 GEMMs (A resident) ========
    big_stage<false>(nullptr, false, g_actB, mat ? g_G2 : g_G1, gm0, gj0, As, Bs);
    grid_barrier();

    // ======== S6: combine d1 -> actA ========
    {
        int tau = bid & 15, obg = bid >> 4;    // 8 groups of OT=2
        combine_dec<32, 16, 2>(g_actB, g_G1, g_G2, h_d1, s,
                               g_actA, 16, tau, obg * 2, Hs);
    }
    grid_barrier();

    // ======== S7: d2 GEMMs (A resident) ========
    big_stage<false>(nullptr, false, g_actA, mat ? g_G2 : g_G1, gm0, gj0, As, Bs);
    grid_barrier();

    // ======== S8: final combine d2 -> out (N, T) ========
    if (bid < 32) {
        const int tau = bid;
        const float sv[4] = { s[0], s[1], s[2], s[3] };
        for (int idx = tid; idx < 144; idx += 256) {   // CI=16, OT=1
            int b = idx % 3, a = (idx / 3) % 3, i = idx / 9;
            Hs[idx] = fold_H(&h_d2[i * 3], sv, a, b);
        }
        __syncthreads();
        if (tid < NN) {
            const int n = tid;
            float acc = 0.f;
            #pragma unroll
            for (int a = 0; a < 3; a++) {
                int src = tau - a; if (src < 0) src += TT;
                if (src & 1) continue;
                int tl = src >> 1;
                #pragma unroll
                for (int i = 0; i < 16; i++) {
                    float v0 = __ldcg(&g_actA[(tl * 16 + i) * NN + n]);
                    float v1 = __ldcg(&g_G1[(tl * 16 + i) * NN + n]);
                    float v2 = __ldcg(&g_G2[(tl * 16 + i) * NN + n]);
                    acc += Hs[(i * 3 + a) * 3 + 0] * v0
                         + Hs[(i * 3 + a) * 3 + 1] * v1
                         + Hs[(i * 3 + a) * 3 + 2] * v2;
                }
            }
            out[n * TT + tau] = acc;
        }
    }
}

// ---------------- launch ---------------------------------------------------------
extern "C" void kernel_launch(void* const* d_in, const int* in_sizes, int n_in,
                              void* d_out, int out_size)
{
    const float* X    = (const float*)d_in[0];
    const float* Sg   = (const float*)d_in[1];
    const float* s    = (const float*)d_in[2];
    const float* h_e1 = (const float*)d_in[3];
    const float* h_e2 = (const float*)d_in[4];
    const float* h_d1 = (const float*)d_in[5];
    const float* h_d2 = (const float*)d_in[6];
    float* out = (float*)d_out;

    mega<<<NB, 256>>>(X, Sg, s, h_e1, h_e2, h_d1, h_d2, out);
}